// round 2
// baseline (speedup 1.0000x reference)
#include <cuda_runtime.h>
#include <cuda_bf16.h>
#include <math.h>

#define LEAKK 0.01f
#define EPSS  1e-5f

// ---------------- scratch (device globals; no allocation) ----------------
__device__ float g_y0[16*64*64*64];    // enc0 raw out  (B,64,64,64)
__device__ float g_y1[16*128*32*32];   // enc1 raw out
__device__ float g_y2[16*256*16*16];   // enc2 raw out
__device__ float g_z [16*256*8*8];     // enc3 out (z)
__device__ float g_q [16*256*8*8];     // quantized (NCHW)
__device__ float g_d0[16*128*32*32];   // dec0 raw out
__device__ float g_d1[16*64*64*64];    // dec1 raw out
__device__ float g_d2[16*32*128*128];  // dec2 raw out
__device__ float g_wt[1707008];        // transposed encoder weights
__device__ float g_scale[6*256];
__device__ float g_shift[6*256];
__device__ float g_cnorm[512];
__device__ float g_rowloss[1024];

// ---------------- weight transpose: OIHW -> [(ci*16+kh*4+kw)][co] --------
__global__ void wtrans(const float* __restrict__ w, float* __restrict__ wt,
                       int Ci, int Co) {
    int n = Co * Ci * 16;
    for (int i = blockIdx.x * blockDim.x + threadIdx.x; i < n;
         i += gridDim.x * blockDim.x) {
        int co = i / (Ci * 16);
        int r  = i % (Ci * 16);
        wt[r * Co + co] = w[i];
    }
}

// ---------------- stride-2 k=4 pad=1 conv, fused input BN+LeakyReLU ------
// grid (Wo/TW, Ho, B), block COUT threads
template<int CIN, int COUT, int H, int W, int TW>
__global__ void conv_s2(const float* __restrict__ x, const float* __restrict__ wt,
                        const float* __restrict__ bias,
                        const float* __restrict__ scale, const float* __restrict__ shift,
                        float* __restrict__ y) {
    constexpr int Ho = H / 2, Wo = W / 2;
    constexpr int TC = 2 * TW + 2;
    __shared__ float tile[CIN * 4 * TC];
    const int b = blockIdx.z, oh = blockIdx.y, ow0 = blockIdx.x * TW;
    const int co = threadIdx.x;
    const int ih0 = 2 * oh - 1, iw0 = 2 * ow0 - 1;

    for (int i = co; i < CIN * 4 * TC; i += COUT) {
        int ci = i / (4 * TC);
        int rem = i % (4 * TC);
        int r = rem / TC, c = rem % TC;
        int ih = ih0 + r, iw = iw0 + c;
        float v = 0.f;
        if (ih >= 0 && ih < H && iw >= 0 && iw < W) {
            v = x[((b * CIN + ci) * H + ih) * W + iw];
            if (scale) {
                v = v * scale[ci] + shift[ci];
                v = (v >= 0.f) ? v : LEAKK * v;
            }
        }
        tile[i] = v;
    }
    __syncthreads();

    float acc[TW];
#pragma unroll
    for (int t = 0; t < TW; t++) acc[t] = 0.f;

    for (int ci = 0; ci < CIN; ci++) {
#pragma unroll
        for (int kh = 0; kh < 4; kh++) {
            float r[TC];
#pragma unroll
            for (int c = 0; c < TC; c++) r[c] = tile[(ci * 4 + kh) * TC + c];
#pragma unroll
            for (int kw = 0; kw < 4; kw++) {
                float wv = wt[(ci * 16 + kh * 4 + kw) * COUT + co];
#pragma unroll
                for (int t = 0; t < TW; t++) acc[t] += wv * r[2 * t + kw];
            }
        }
    }
    float bv = bias[co];
#pragma unroll
    for (int t = 0; t < TW; t++)
        y[((b * COUT + co) * Ho + oh) * Wo + ow0 + t] = acc[t] + bv;
}

// ---------------- BN batch stats -> per-channel scale/shift --------------
__global__ void bnstats(const float* __restrict__ y, int C, int HW,
                        const float* __restrict__ g, const float* __restrict__ bb,
                        float* __restrict__ scale, float* __restrict__ shift) {
    int c = blockIdx.x;
    int n = 16 * HW;
    float s = 0.f, s2 = 0.f;
    for (int i = threadIdx.x; i < n; i += blockDim.x) {
        int b = i / HW, r = i % HW;
        float v = y[(b * C + c) * HW + r];
        s += v; s2 += v * v;
    }
    __shared__ float sh[256], sh2[256];
    sh[threadIdx.x] = s; sh2[threadIdx.x] = s2;
    __syncthreads();
    for (int o = 128; o > 0; o >>= 1) {
        if (threadIdx.x < o) { sh[threadIdx.x] += sh[threadIdx.x + o];
                               sh2[threadIdx.x] += sh2[threadIdx.x + o]; }
        __syncthreads();
    }
    if (threadIdx.x == 0) {
        float m = sh[0] / n;
        float v = sh2[0] / n - m * m;
        float sc = g[c] * rsqrtf(v + EPSS);
        scale[c] = sc;
        shift[c] = bb[c] - m * sc;
    }
}

// ---------------- codebook squared norms ----------------------------------
__global__ void cnormk(const float* __restrict__ cb, float* __restrict__ cn) {
    int c = blockIdx.x;
    float v = cb[c * 256 + threadIdx.x];
    __shared__ float sh[256];
    sh[threadIdx.x] = v * v;
    __syncthreads();
    for (int o = 128; o > 0; o >>= 1) {
        if (threadIdx.x < o) sh[threadIdx.x] += sh[threadIdx.x + o];
        __syncthreads();
    }
    if (threadIdx.x == 0) cn[c] = sh[0];
}

// ---------------- vector quantizer ---------------------------------------
// block per (b,h,w) row; 256 threads (8 warps)
__global__ void vqk(const float* __restrict__ z, const float* __restrict__ cb,
                    const float* __restrict__ cn, float* __restrict__ q,
                    float* __restrict__ rowloss,
                    float* __restrict__ out_idx, float* __restrict__ out_mind) {
    int row = blockIdx.x;
    int b = row >> 6, hw = row & 63;
    int tid = threadIdx.x, lane = tid & 31, warp = tid >> 5;
    __shared__ float zf[256];
    __shared__ float red[256];

    zf[tid] = z[(b * 256 + tid) * 64 + hw];
    red[tid] = zf[tid] * zf[tid];
    __syncthreads();
    for (int o = 128; o > 0; o >>= 1) {
        if (tid < o) red[tid] += red[tid + o];
        __syncthreads();
    }
    float znorm = red[0];
    __syncthreads();

    float best = 3.4e38f; int bidx = 1 << 20;
    for (int code = warp; code < 512; code += 8) {
        const float* cr = cb + code * 256;
        float dot = 0.f;
#pragma unroll
        for (int k = 0; k < 8; k++) dot += cr[lane + 32 * k] * zf[lane + 32 * k];
#pragma unroll
        for (int o = 16; o > 0; o >>= 1) dot += __shfl_down_sync(0xffffffffu, dot, o);
        if (lane == 0) {
            float d2 = znorm - 2.f * dot + cn[code];
            if (d2 < best || (d2 == best && code < bidx)) { best = d2; bidx = code; }
        }
    }
    __shared__ float wbest[8]; __shared__ int widx[8];
    if (lane == 0) { wbest[warp] = best; widx[warp] = bidx; }
    __syncthreads();
    if (tid == 0) {
        float bb = wbest[0]; int bi = widx[0];
        for (int w = 1; w < 8; w++)
            if (wbest[w] < bb || (wbest[w] == bb && widx[w] < bi)) { bb = wbest[w]; bi = widx[w]; }
        wbest[0] = bb; widx[0] = bi;
    }
    __syncthreads();
    int idx = widx[0];
    float mind = wbest[0];

    float qv = cb[idx * 256 + tid];
    q[(b * 256 + tid) * 64 + hw] = qv;
    float diff = qv - zf[tid];
    red[tid] = diff * diff;
    __syncthreads();
    for (int o = 128; o > 0; o >>= 1) {
        if (tid < o) red[tid] += red[tid + o];
        __syncthreads();
    }
    if (tid == 0) {
        rowloss[row] = red[0];
        out_idx[row] = (float)idx;
        out_mind[row] = mind;
    }
}

__global__ void lossfin(const float* __restrict__ rowloss, float* __restrict__ out) {
    __shared__ float sh[256];
    float s = 0.f;
    for (int i = threadIdx.x; i < 1024; i += 256) s += rowloss[i];
    sh[threadIdx.x] = s; __syncthreads();
    for (int o = 128; o > 0; o >>= 1) {
        if (threadIdx.x < o) sh[threadIdx.x] += sh[threadIdx.x + o];
        __syncthreads();
    }
    if (threadIdx.x == 0) {
        float L = sh[0] / (1024.f * 256.f);
        out[786432] = L;   // commitment_loss
        out[786433] = L;   // codebook_loss (same forward value)
    }
}

// ---------------- ConvTranspose (stride == k, pad 0), fused input BN+LReLU
// grid (W/P, H, B); each block processes P input pixels
template<int CIN, int COUT, int K, int H, int W, int P, int NT>
__global__ void convt(const float* __restrict__ x, const float* __restrict__ w,
                      const float* __restrict__ bias,
                      const float* __restrict__ scale, const float* __restrict__ shift,
                      float* __restrict__ y) {
    constexpr int COKK = COUT * K * K;
    constexpr int Hout = H * K, Wout = W * K;
    __shared__ float sx[CIN * P];
    int b = blockIdx.z, ih = blockIdx.y, iw0 = blockIdx.x * P;

    for (int i = threadIdx.x; i < CIN * P; i += NT) {
        int c = i / P, p = i % P;
        float v = x[((b * CIN + c) * H + ih) * W + iw0 + p];
        if (scale) {
            v = v * scale[c] + shift[c];
            v = (v >= 0.f) ? v : LEAKK * v;
        }
        sx[i] = v;
    }
    __syncthreads();

    for (int oidx = threadIdx.x; oidx < COKK; oidx += NT) {
        int co = oidx / (K * K);
        int rem = oidx % (K * K);
        int ki = rem / K, kj = rem % K;
        float acc[P];
#pragma unroll
        for (int p = 0; p < P; p++) acc[p] = 0.f;
        for (int c = 0; c < CIN; c++) {
            float wv = w[c * COKK + oidx];
#pragma unroll
            for (int p = 0; p < P; p++) acc[p] += wv * sx[c * P + p];
        }
        float bv = bias[co];
#pragma unroll
        for (int p = 0; p < P; p++)
            y[((b * COUT + co) * Hout + ih * K + ki) * Wout + (iw0 + p) * K + kj]
                = acc[p] + bv;
    }
}

// ---------------- final 1x1 conv + tanh, fused input BN+LReLU ------------
__global__ void final1x1(const float* __restrict__ h, const float* __restrict__ w3,
                         const float* __restrict__ b3,
                         const float* __restrict__ scale, const float* __restrict__ shift,
                         float* __restrict__ out) {
    __shared__ float sw[96], ssc[32], ssh[32], sb[3];
    if (threadIdx.x < 96) sw[threadIdx.x] = w3[threadIdx.x];
    if (threadIdx.x < 32) { ssc[threadIdx.x] = scale[threadIdx.x];
                            ssh[threadIdx.x] = shift[threadIdx.x]; }
    if (threadIdx.x < 3) sb[threadIdx.x] = b3[threadIdx.x];
    __syncthreads();
    const int HW = 128 * 128;
    int gid = blockIdx.x * blockDim.x + threadIdx.x;   // over 16*HW
    int b = gid / HW, r = gid % HW;
    float a0 = 0.f, a1 = 0.f, a2 = 0.f;
#pragma unroll 8
    for (int c = 0; c < 32; c++) {
        float v = h[(b * 32 + c) * HW + r];
        v = v * ssc[c] + ssh[c];
        v = (v >= 0.f) ? v : LEAKK * v;
        a0 += v * sw[c];
        a1 += v * sw[32 + c];
        a2 += v * sw[64 + c];
    }
    out[(b * 3 + 0) * HW + r] = tanhf(a0 + sb[0]);
    out[(b * 3 + 1) * HW + r] = tanhf(a1 + sb[1]);
    out[(b * 3 + 2) * HW + r] = tanhf(a2 + sb[2]);
}

// ------------------------------------------------------------------------
extern "C" void kernel_launch(void* const* d_in, const int* in_sizes, int n_in,
                              void* d_out, int out_size) {
    (void)n_in; (void)out_size;

    const float* x = (const float*)d_in[0];
    const float *ew0, *eb0, *eg0, *ebb0;
    const float *ew1, *eb1, *eg1, *ebb1;
    const float *ew2, *eb2, *eg2, *ebb2;
    const float *ew3, *eb3;

    // Detect input ordering from sizes.
    // Signature order: d_in[3] = ebn_g0 (64 elems).
    // Dict order:      d_in[3] = enc_w1 (131072 elems).
    if (in_sizes[3] == 64) {
        // interleaved (reference-signature) order
        ew0 = (const float*)d_in[1];  eb0 = (const float*)d_in[2];
        eg0 = (const float*)d_in[3];  ebb0 = (const float*)d_in[4];
        ew1 = (const float*)d_in[5];  eb1 = (const float*)d_in[6];
        eg1 = (const float*)d_in[7];  ebb1 = (const float*)d_in[8];
        ew2 = (const float*)d_in[9];  eb2 = (const float*)d_in[10];
        eg2 = (const float*)d_in[11]; ebb2 = (const float*)d_in[12];
        ew3 = (const float*)d_in[13]; eb3 = (const float*)d_in[14];
    } else {
        // setup_inputs dict order: enc_w0..enc_b3 first, then ebn pairs
        ew0 = (const float*)d_in[1];  eb0 = (const float*)d_in[2];
        ew1 = (const float*)d_in[3];  eb1 = (const float*)d_in[4];
        ew2 = (const float*)d_in[5];  eb2 = (const float*)d_in[6];
        ew3 = (const float*)d_in[7];  eb3 = (const float*)d_in[8];
        eg0 = (const float*)d_in[9];  ebb0 = (const float*)d_in[10];
        eg1 = (const float*)d_in[11]; ebb1 = (const float*)d_in[12];
        eg2 = (const float*)d_in[13]; ebb2 = (const float*)d_in[14];
    }

    const float* cb   = (const float*)d_in[15];
    const float* dw0  = (const float*)d_in[16];
    const float* db0  = (const float*)d_in[17];
    const float* dg0  = (const float*)d_in[18];
    const float* dbb0 = (const float*)d_in[19];
    const float* dw1  = (const float*)d_in[20];
    const float* db1  = (const float*)d_in[21];
    const float* dg1  = (const float*)d_in[22];
    const float* dbb1 = (const float*)d_in[23];
    const float* dw2  = (const float*)d_in[24];
    const float* db2  = (const float*)d_in[25];
    const float* dg2  = (const float*)d_in[26];
    const float* dbb2 = (const float*)d_in[27];
    const float* dw3  = (const float*)d_in[28];
    const float* db3  = (const float*)d_in[29];
    float* out = (float*)d_out;

    float *y0, *y1, *y2, *z, *q, *d0, *d1, *d2, *wt, *sc, *sf, *cn, *rl;
    cudaGetSymbolAddress((void**)&y0, g_y0);
    cudaGetSymbolAddress((void**)&y1, g_y1);
    cudaGetSymbolAddress((void**)&y2, g_y2);
    cudaGetSymbolAddress((void**)&z,  g_z);
    cudaGetSymbolAddress((void**)&q,  g_q);
    cudaGetSymbolAddress((void**)&d0, g_d0);
    cudaGetSymbolAddress((void**)&d1, g_d1);
    cudaGetSymbolAddress((void**)&d2, g_d2);
    cudaGetSymbolAddress((void**)&wt, g_wt);
    cudaGetSymbolAddress((void**)&sc, g_scale);
    cudaGetSymbolAddress((void**)&sf, g_shift);
    cudaGetSymbolAddress((void**)&cn, g_cnorm);
    cudaGetSymbolAddress((void**)&rl, g_rowloss);

    // transposed-weight offsets
    float* wt0 = wt;                 // 3*16*64    = 3072
    float* wt1 = wt + 3072;          // 64*16*128  = 131072
    float* wt2 = wt + 134144;        // 128*16*256 = 524288
    float* wt3 = wt + 658432;        // 256*16*256 = 1048576

    wtrans<<<8,   256>>>(ew0, wt0,   3,  64);
    wtrans<<<128, 256>>>(ew1, wt1,  64, 128);
    wtrans<<<512, 256>>>(ew2, wt2, 128, 256);
    wtrans<<<1024,256>>>(ew3, wt3, 256, 256);
    cnormk<<<512, 256>>>(cb, cn);

    // ---- encoder ----
    conv_s2<3,   64, 128, 128, 4><<<dim3(16, 64, 16),  64>>>(x,  wt0, eb0, nullptr, nullptr, y0);
    bnstats<<<64, 256>>>(y0,  64, 64*64, eg0, ebb0, sc + 0*256, sf + 0*256);
    conv_s2<64, 128,  64,  64, 4><<<dim3(8, 32, 16), 128>>>(y0, wt1, eb1, sc + 0*256, sf + 0*256, y1);
    bnstats<<<128, 256>>>(y1, 128, 32*32, eg1, ebb1, sc + 1*256, sf + 1*256);
    conv_s2<128,256,  32,  32, 4><<<dim3(4, 16, 16), 256>>>(y1, wt2, eb2, sc + 1*256, sf + 1*256, y2);
    bnstats<<<256, 256>>>(y2, 256, 16*16, eg2, ebb2, sc + 2*256, sf + 2*256);
    conv_s2<256,256,  16,  16, 4><<<dim3(2, 8, 16),  256>>>(y2, wt3, eb3, sc + 2*256, sf + 2*256, z);

    // ---- vector quantizer ----
    vqk<<<1024, 256>>>(z, cb, cn, q, rl, out + 786434, out + 786434 + 1024);
    lossfin<<<1, 256>>>(rl, out);

    // ---- decoder ----
    convt<256, 128, 4,  8,  8, 4, 256><<<dim3(2, 8, 16),  256>>>(q,  dw0, db0, nullptr, nullptr, d0);
    bnstats<<<128, 256>>>(d0, 128, 32*32, dg0, dbb0, sc + 3*256, sf + 3*256);
    convt<128,  64, 2, 32, 32, 4, 256><<<dim3(8, 32, 16), 256>>>(d0, dw1, db1, sc + 3*256, sf + 3*256, d1);
    bnstats<<<64, 256>>>(d1,  64, 64*64, dg1, dbb1, sc + 4*256, sf + 4*256);
    convt<64,   32, 2, 64, 64, 8, 128><<<dim3(8, 64, 16), 128>>>(d1, dw2, db2, sc + 4*256, sf + 4*256, d2);
    bnstats<<<32, 256>>>(d2,  32, 128*128, dg2, dbb2, sc + 5*256, sf + 5*256);

    final1x1<<<1024, 256>>>(d2, dw3, db3, sc + 5*256, sf + 5*256, out);
}

// round 6
// speedup vs baseline: 1.8074x; 1.8074x over previous
#include <cuda_runtime.h>
#include <cuda_bf16.h>
#include <math.h>

#define LEAKK 0.01f
#define EPSS  1e-5f

// packed fp32x2 FMA (FFMA2) — B300 only via PTX fma.rn.f32x2
#define FMA2(acc, a, b) \
    asm("fma.rn.f32x2 %0, %1, %2, %0;" : "+l"(acc) : "l"(a), "l"(b))

__device__ __forceinline__ float2 unpk(unsigned long long p) {
    unsigned int lo, hi;
    asm("mov.b64 {%0,%1}, %2;" : "=r"(lo), "=r"(hi) : "l"(p));
    return make_float2(__uint_as_float(lo), __uint_as_float(hi));
}

// ---------------- scratch (device globals; no allocation) ----------------
__device__ float g_y0[16*64*64*64];
__device__ float g_y1[16*128*32*32];
__device__ float g_y2[16*256*16*16];
__device__ float g_z [16*256*8*8];
__device__ float g_q [16*256*8*8];
__device__ float g_d0[16*128*32*32];
__device__ float g_d1[16*64*64*64];
__device__ float g_d2[16*32*128*128];
__device__ float g_wt[1707008];
__device__ float g_part[4*262144];
__device__ float g_scale[6*256];
__device__ float g_shift[6*256];
__device__ float g_cnorm[512];
__device__ float g_rowloss[1024];
__device__ float2 g_bnp[256*8];

// ---------------- smem-tiled transpose: w[Co][K] -> wt[K][Co] ------------
__global__ void wtrans(const float* __restrict__ in, float* __restrict__ outp,
                       int R /*Co*/, int Ccol /*Ci*16*/) {
    __shared__ float t[32][33];
    int bx = blockIdx.x * 32, by = blockIdx.y * 32;
    int tx = threadIdx.x, ty = threadIdx.y;
#pragma unroll
    for (int j = 0; j < 4; j++) {
        int xx = bx + tx, yy = by + ty + j * 8;
        if (xx < Ccol && yy < R) t[ty + j * 8][tx] = in[yy * Ccol + xx];
    }
    __syncthreads();
#pragma unroll
    for (int j = 0; j < 4; j++) {
        int xx = by + tx, yy = bx + ty + j * 8;   // out[yy(=k)][xx(=co)]
        if (xx < R && yy < Ccol) outp[yy * R + xx] = t[tx][ty + j * 8];
    }
}

// ---------------- conv (k=4,s=2,p=1) as register-tiled GEMM --------------
// block: 256 thr -> 64 co x 64 pixel tile; k-chunk = 16 (one ci)
template<int CIN, int COUT, int H, int W, bool BN, bool SPLIT>
__global__ void __launch_bounds__(256)
gconv(const float* __restrict__ x, const float* __restrict__ wt,
      const float* __restrict__ bias,
      const float* __restrict__ scale, const float* __restrict__ shift,
      float* __restrict__ out) {
    constexpr int Ho = H / 2, Wo = W / 2, HoWo = Ho * Wo;
    constexpr int NPIX = 16 * HoWo;
    constexpr int NCH = SPLIT ? 64 : CIN;

    __shared__ float Asd[2][16][128];
    __shared__ float Bs [2][16][64];

    const int tid = threadIdx.x;
    const int tx = tid & 15, ty = tid >> 4;
    const int p0 = blockIdx.x * 64;
    const int co0 = blockIdx.y * 64;
    const int ci0 = SPLIT ? blockIdx.z * 64 : 0;

    const int pp = tid & 63;
    const int cc = tid & 63;
    int kkj[4], boff[4];
    bool val[4];
    {
        int gp = p0 + pp;
        int b = gp / HoWo, r = gp % HoWo;
        int oh = r / Wo, ow = r % Wo;
#pragma unroll
        for (int j = 0; j < 4; j++) {
            int kk = (tid >> 6) + 4 * j;
            int kh = kk >> 2, kw = kk & 3;
            int ih = 2 * oh - 1 + kh, iw = 2 * ow - 1 + kw;
            val[j] = (ih >= 0) && (ih < H) && (iw >= 0) && (iw < W);
            kkj[j] = kk;
            boff[j] = (b * CIN + 0) * H * W + ih * W + iw;
        }
    }

    float bv[4], av[4];
    auto gather = [&](int c) {
        int ci = ci0 + c;
        float sc = 1.f, sf = 0.f;
        if (BN) { sc = scale[ci]; sf = shift[ci]; }
#pragma unroll
        for (int j = 0; j < 4; j++) {
            float v = 0.f;
            // FIX: BN+LeakyReLU only for in-bounds pixels — the conv pads the
            // NORMALIZED feature map with zeros, so OOB must stay exactly 0.
            if (val[j]) {
                v = x[boff[j] + ci * (H * W)];
                if (BN) { v = v * sc + sf; v = fmaxf(v, LEAKK * v); }
            }
            bv[j] = v;
            av[j] = wt[(ci * 16 + kkj[j]) * COUT + co0 + cc];
        }
    };
    auto stobuf = [&](int nb) {
#pragma unroll
        for (int j = 0; j < 4; j++) {
            Bs[nb][kkj[j]][pp] = bv[j];
            *(float2*)&Asd[nb][kkj[j]][2 * cc] = make_float2(av[j], av[j]);
        }
    };

    gather(0);
    stobuf(0);
    __syncthreads();

    unsigned long long acc[4][2];
#pragma unroll
    for (int i = 0; i < 4; i++) { acc[i][0] = 0ULL; acc[i][1] = 0ULL; }

    for (int c = 0; c < NCH; c++) {
        int cur = c & 1;
        bool more = (c + 1) < NCH;
        if (more) gather(c + 1);
#pragma unroll
        for (int k = 0; k < 16; k++) {
            ulonglong2 b2  = *(const ulonglong2*)&Bs [cur][k][4 * tx];
            ulonglong2 a01 = *(const ulonglong2*)&Asd[cur][k][8 * ty];
            ulonglong2 a23 = *(const ulonglong2*)&Asd[cur][k][8 * ty + 4];
            FMA2(acc[0][0], a01.x, b2.x); FMA2(acc[0][1], a01.x, b2.y);
            FMA2(acc[1][0], a01.y, b2.x); FMA2(acc[1][1], a01.y, b2.y);
            FMA2(acc[2][0], a23.x, b2.x); FMA2(acc[2][1], a23.x, b2.y);
            FMA2(acc[3][0], a23.y, b2.x); FMA2(acc[3][1], a23.y, b2.y);
        }
        if (more) stobuf(cur ^ 1);
        __syncthreads();
    }

    const int b = p0 / HoWo;
    const int rb = (p0 % HoWo) + 4 * tx;
    float* po = out;
    if (SPLIT) po += blockIdx.z * (COUT * NPIX);
#pragma unroll
    for (int i = 0; i < 4; i++) {
        int co = co0 + 4 * ty + i;
        float bvs = SPLIT ? 0.f : bias[co];
        float2 u0 = unpk(acc[i][0]);
        float2 u1 = unpk(acc[i][1]);
        float4 o = make_float4(u0.x + bvs, u0.y + bvs, u1.x + bvs, u1.y + bvs);
        *(float4*)&po[(b * COUT + co) * HoWo + rb] = o;
    }
}

// ---------------- ConvTranspose (stride==k) as register-tiled GEMM -------
// no padding -> unconditional BN on input is correct here
template<int CIN, int COUT, int K, int H, int W, bool BN>
__global__ void __launch_bounds__(256)
gconvt(const float* __restrict__ x, const float* __restrict__ w,
       const float* __restrict__ bias,
       const float* __restrict__ scale, const float* __restrict__ shift,
       float* __restrict__ out) {
    constexpr int HW = H * W;
    constexpr int KK = K * K;
    constexpr int M = COUT * KK;
    constexpr int Hout = H * K, Wout = W * K;
    constexpr int NCH = CIN / 16;

    __shared__ float Asd[2][16][128];
    __shared__ float Bs [2][16][64];

    const int tid = threadIdx.x;
    const int tx = tid & 15, ty = tid >> 4;
    const int p0 = blockIdx.x * 64;
    const int m0 = blockIdx.y * 64;

    const int pp = tid & 63;
    const int cc = tid & 63;
    const int cj = tid >> 6;
    int boff;
    {
        int gp = p0 + pp;
        int b = gp / HW, r = gp % HW;
        boff = b * CIN * HW + r;
    }

    float bvr[4], avr[4];
    auto gather = [&](int c) {
        int c0 = c * 16;
#pragma unroll
        for (int j = 0; j < 4; j++) {
            int ch = c0 + cj + 4 * j;
            float v = x[boff + ch * HW];
            if (BN) {
                float sc = scale[ch], sf = shift[ch];
                v = v * sc + sf; v = fmaxf(v, LEAKK * v);
            }
            bvr[j] = v;
            avr[j] = w[ch * M + m0 + cc];
        }
    };
    auto stobuf = [&](int nb) {
#pragma unroll
        for (int j = 0; j < 4; j++) {
            int kk = cj + 4 * j;
            Bs[nb][kk][pp] = bvr[j];
            *(float2*)&Asd[nb][kk][2 * cc] = make_float2(avr[j], avr[j]);
        }
    };

    gather(0);
    stobuf(0);
    __syncthreads();

    unsigned long long acc[4][2];
#pragma unroll
    for (int i = 0; i < 4; i++) { acc[i][0] = 0ULL; acc[i][1] = 0ULL; }

    for (int c = 0; c < NCH; c++) {
        int cur = c & 1;
        bool more = (c + 1) < NCH;
        if (more) gather(c + 1);
#pragma unroll
        for (int k = 0; k < 16; k++) {
            ulonglong2 b2  = *(const ulonglong2*)&Bs [cur][k][4 * tx];
            ulonglong2 a01 = *(const ulonglong2*)&Asd[cur][k][8 * ty];
            ulonglong2 a23 = *(const ulonglong2*)&Asd[cur][k][8 * ty + 4];
            FMA2(acc[0][0], a01.x, b2.x); FMA2(acc[0][1], a01.x, b2.y);
            FMA2(acc[1][0], a01.y, b2.x); FMA2(acc[1][1], a01.y, b2.y);
            FMA2(acc[2][0], a23.x, b2.x); FMA2(acc[2][1], a23.x, b2.y);
            FMA2(acc[3][0], a23.y, b2.x); FMA2(acc[3][1], a23.y, b2.y);
        }
        if (more) stobuf(cur ^ 1);
        __syncthreads();
    }

    const int b = p0 / HW;
    const int rr = (p0 % HW) + 4 * tx;
    int ihh[4], iww[4];
#pragma unroll
    for (int l = 0; l < 4; l++) { ihh[l] = (rr + l) / W; iww[l] = (rr + l) % W; }
#pragma unroll
    for (int i = 0; i < 4; i++) {
        int m = m0 + 4 * ty + i;
        int co = m / KK, rem = m % KK;
        int ki = rem / K, kj = rem % K;
        float bvs = bias[co];
        float2 u0 = unpk(acc[i][0]);
        float2 u1 = unpk(acc[i][1]);
        float f[4] = {u0.x, u0.y, u1.x, u1.y};
#pragma unroll
        for (int l = 0; l < 4; l++) {
            out[((b * COUT + co) * Hout + ihh[l] * K + ki) * Wout + iww[l] * K + kj]
                = f[l] + bvs;
        }
    }
}

// ---------------- enc3 K-split combine + bias -----------------------------
__global__ void zcombine(const float* __restrict__ part, const float* __restrict__ bias,
                         float* __restrict__ z) {
    int i = blockIdx.x * blockDim.x + threadIdx.x;
    int co = (i >> 6) & 255;
    z[i] = part[i] + part[i + 262144] + part[i + 2*262144] + part[i + 3*262144]
           + bias[co];
}

// ---------------- BN batch stats: two-phase ------------------------------
__global__ void bnpart(const float* __restrict__ y, int C, int HW,
                       float2* __restrict__ part) {
    int c = blockIdx.x, s = blockIdx.y;
    int seg = HW / 8, r0 = s * seg;
    float sm = 0.f, s2 = 0.f;
    for (int b = 0; b < 16; b++) {
        const float* p = y + (b * C + c) * HW;
        for (int r = r0 + threadIdx.x; r < r0 + seg; r += 256) {
            float v = p[r];
            sm += v; s2 += v * v;
        }
    }
    __shared__ float sh[256], sh2[256];
    sh[threadIdx.x] = sm; sh2[threadIdx.x] = s2;
    __syncthreads();
    for (int o = 128; o > 0; o >>= 1) {
        if (threadIdx.x < o) { sh[threadIdx.x] += sh[threadIdx.x + o];
                               sh2[threadIdx.x] += sh2[threadIdx.x + o]; }
        __syncthreads();
    }
    if (threadIdx.x == 0) part[c * 8 + s] = make_float2(sh[0], sh2[0]);
}

__global__ void bnfin(const float2* __restrict__ part,
                      const float* __restrict__ g, const float* __restrict__ bb,
                      float* __restrict__ scale, float* __restrict__ shift,
                      int C, float invn) {
    int c = threadIdx.x;
    if (c >= C) return;
    float sm = 0.f, s2 = 0.f;
#pragma unroll
    for (int s = 0; s < 8; s++) { float2 p = part[c * 8 + s]; sm += p.x; s2 += p.y; }
    float m = sm * invn;
    float v = s2 * invn - m * m;
    float sc = g[c] * rsqrtf(v + EPSS);
    scale[c] = sc;
    shift[c] = bb[c] - m * sc;
}

// ---------------- codebook squared norms ----------------------------------
__global__ void cnormk(const float* __restrict__ cb, float* __restrict__ cn) {
    int c = blockIdx.x;
    float v = cb[c * 256 + threadIdx.x];
    __shared__ float sh[256];
    sh[threadIdx.x] = v * v;
    __syncthreads();
    for (int o = 128; o > 0; o >>= 1) {
        if (threadIdx.x < o) sh[threadIdx.x] += sh[threadIdx.x + o];
        __syncthreads();
    }
    if (threadIdx.x == 0) cn[c] = sh[0];
}

// ---------------- vector quantizer ---------------------------------------
__global__ void vqk(const float* __restrict__ z, const float* __restrict__ cb,
                    const float* __restrict__ cn, float* __restrict__ q,
                    float* __restrict__ rowloss,
                    float* __restrict__ out_idx, float* __restrict__ out_mind) {
    int row = blockIdx.x;
    int b = row >> 6, hw = row & 63;
    int tid = threadIdx.x, lane = tid & 31, warp = tid >> 5;
    __shared__ float zf[256];
    __shared__ float red[256];

    zf[tid] = z[(b * 256 + tid) * 64 + hw];
    red[tid] = zf[tid] * zf[tid];
    __syncthreads();
    for (int o = 128; o > 0; o >>= 1) {
        if (tid < o) red[tid] += red[tid + o];
        __syncthreads();
    }
    float znorm = red[0];
    __syncthreads();

    float best = 3.4e38f; int bidx = 1 << 20;
    for (int code = warp; code < 512; code += 8) {
        const float* cr = cb + code * 256;
        float dot = 0.f;
#pragma unroll
        for (int k = 0; k < 8; k++) dot += cr[lane + 32 * k] * zf[lane + 32 * k];
#pragma unroll
        for (int o = 16; o > 0; o >>= 1) dot += __shfl_down_sync(0xffffffffu, dot, o);
        if (lane == 0) {
            float d2 = znorm - 2.f * dot + cn[code];
            if (d2 < best || (d2 == best && code < bidx)) { best = d2; bidx = code; }
        }
    }
    __shared__ float wbest[8]; __shared__ int widx[8];
    if (lane == 0) { wbest[warp] = best; widx[warp] = bidx; }
    __syncthreads();
    if (tid == 0) {
        float bb = wbest[0]; int bi = widx[0];
        for (int w = 1; w < 8; w++)
            if (wbest[w] < bb || (wbest[w] == bb && widx[w] < bi)) { bb = wbest[w]; bi = widx[w]; }
        wbest[0] = bb; widx[0] = bi;
    }
    __syncthreads();
    int idx = widx[0];
    float mind = wbest[0];

    float qv = cb[idx * 256 + tid];
    q[(b * 256 + tid) * 64 + hw] = qv;
    float diff = qv - zf[tid];
    red[tid] = diff * diff;
    __syncthreads();
    for (int o = 128; o > 0; o >>= 1) {
        if (tid < o) red[tid] += red[tid + o];
        __syncthreads();
    }
    if (tid == 0) {
        rowloss[row] = red[0];
        out_idx[row] = (float)idx;
        out_mind[row] = mind;
    }
}

__global__ void lossfin(const float* __restrict__ rowloss, float* __restrict__ out) {
    __shared__ float sh[256];
    float s = 0.f;
    for (int i = threadIdx.x; i < 1024; i += 256) s += rowloss[i];
    sh[threadIdx.x] = s; __syncthreads();
    for (int o = 128; o > 0; o >>= 1) {
        if (threadIdx.x < o) sh[threadIdx.x] += sh[threadIdx.x + o];
        __syncthreads();
    }
    if (threadIdx.x == 0) {
        float L = sh[0] / (1024.f * 256.f);
        out[786432] = L;
        out[786433] = L;
    }
}

// ---------------- final 1x1 conv + tanh, fused input BN+LReLU ------------
__global__ void final1x1(const float* __restrict__ h, const float* __restrict__ w3,
                         const float* __restrict__ b3,
                         const float* __restrict__ scale, const float* __restrict__ shift,
                         float* __restrict__ out) {
    __shared__ float sw[96], ssc[32], ssh[32], sb[3];
    if (threadIdx.x < 96) sw[threadIdx.x] = w3[threadIdx.x];
    if (threadIdx.x < 32) { ssc[threadIdx.x] = scale[threadIdx.x];
                            ssh[threadIdx.x] = shift[threadIdx.x]; }
    if (threadIdx.x < 3) sb[threadIdx.x] = b3[threadIdx.x];
    __syncthreads();
    const int HW = 128 * 128;
    int gid = blockIdx.x * blockDim.x + threadIdx.x;
    int b = gid / HW, r = gid % HW;
    float a0 = 0.f, a1 = 0.f, a2 = 0.f;
#pragma unroll 8
    for (int c = 0; c < 32; c++) {
        float v = h[(b * 32 + c) * HW + r];
        v = v * ssc[c] + ssh[c];
        v = fmaxf(v, LEAKK * v);
        a0 += v * sw[c];
        a1 += v * sw[32 + c];
        a2 += v * sw[64 + c];
    }
    out[(b * 3 + 0) * HW + r] = tanhf(a0 + sb[0]);
    out[(b * 3 + 1) * HW + r] = tanhf(a1 + sb[1]);
    out[(b * 3 + 2) * HW + r] = tanhf(a2 + sb[2]);
}

// ------------------------------------------------------------------------
extern "C" void kernel_launch(void* const* d_in, const int* in_sizes, int n_in,
                              void* d_out, int out_size) {
    (void)n_in; (void)out_size;

    const float* x = (const float*)d_in[0];
    const float *ew0, *eb0, *eg0, *ebb0;
    const float *ew1, *eb1, *eg1, *ebb1;
    const float *ew2, *eb2, *eg2, *ebb2;
    const float *ew3, *eb3;

    if (in_sizes[3] == 64) {
        ew0 = (const float*)d_in[1];  eb0 = (const float*)d_in[2];
        eg0 = (const float*)d_in[3];  ebb0 = (const float*)d_in[4];
        ew1 = (const float*)d_in[5];  eb1 = (const float*)d_in[6];
        eg1 = (const float*)d_in[7];  ebb1 = (const float*)d_in[8];
        ew2 = (const float*)d_in[9];  eb2 = (const float*)d_in[10];
        eg2 = (const float*)d_in[11]; ebb2 = (const float*)d_in[12];
        ew3 = (const float*)d_in[13]; eb3 = (const float*)d_in[14];
    } else {
        ew0 = (const float*)d_in[1];  eb0 = (const float*)d_in[2];
        ew1 = (const float*)d_in[3];  eb1 = (const float*)d_in[4];
        ew2 = (const float*)d_in[5];  eb2 = (const float*)d_in[6];
        ew3 = (const float*)d_in[7];  eb3 = (const float*)d_in[8];
        eg0 = (const float*)d_in[9];  ebb0 = (const float*)d_in[10];
        eg1 = (const float*)d_in[11]; ebb1 = (const float*)d_in[12];
        eg2 = (const float*)d_in[13]; ebb2 = (const float*)d_in[14];
    }

    const float* cb   = (const float*)d_in[15];
    const float* dw0  = (const float*)d_in[16];
    const float* db0  = (const float*)d_in[17];
    const float* dg0  = (const float*)d_in[18];
    const float* dbb0 = (const float*)d_in[19];
    const float* dw1  = (const float*)d_in[20];
    const float* db1  = (const float*)d_in[21];
    const float* dg1  = (const float*)d_in[22];
    const float* dbb1 = (const float*)d_in[23];
    const float* dw2  = (const float*)d_in[24];
    const float* db2  = (const float*)d_in[25];
    const float* dg2  = (const float*)d_in[26];
    const float* dbb2 = (const float*)d_in[27];
    const float* dw3  = (const float*)d_in[28];
    const float* db3  = (const float*)d_in[29];
    float* out = (float*)d_out;

    float *y0, *y1, *y2, *z, *q, *d0, *d1, *d2, *wt, *part, *sc, *sf, *cn, *rl;
    float2* bnp;
    cudaGetSymbolAddress((void**)&y0, g_y0);
    cudaGetSymbolAddress((void**)&y1, g_y1);
    cudaGetSymbolAddress((void**)&y2, g_y2);
    cudaGetSymbolAddress((void**)&z,  g_z);
    cudaGetSymbolAddress((void**)&q,  g_q);
    cudaGetSymbolAddress((void**)&d0, g_d0);
    cudaGetSymbolAddress((void**)&d1, g_d1);
    cudaGetSymbolAddress((void**)&d2, g_d2);
    cudaGetSymbolAddress((void**)&wt, g_wt);
    cudaGetSymbolAddress((void**)&part, g_part);
    cudaGetSymbolAddress((void**)&sc, g_scale);
    cudaGetSymbolAddress((void**)&sf, g_shift);
    cudaGetSymbolAddress((void**)&cn, g_cnorm);
    cudaGetSymbolAddress((void**)&rl, g_rowloss);
    cudaGetSymbolAddress((void**)&bnp, g_bnp);

    float* wt0 = wt;
    float* wt1 = wt + 3072;
    float* wt2 = wt + 134144;
    float* wt3 = wt + 658432;

    dim3 t32(32, 8);
    wtrans<<<dim3(2,   2), t32>>>(ew0, wt0,  64,   48);
    wtrans<<<dim3(32,  4), t32>>>(ew1, wt1, 128, 1024);
    wtrans<<<dim3(64,  8), t32>>>(ew2, wt2, 256, 2048);
    wtrans<<<dim3(128, 8), t32>>>(ew3, wt3, 256, 4096);
    cnormk<<<512, 256>>>(cb, cn);

    // ---- encoder ----
    gconv<3,   64, 128, 128, false, false><<<dim3(1024, 1), 256>>>(x,  wt0, eb0, nullptr, nullptr, y0);
    bnpart<<<dim3(64, 8),  256>>>(y0,  64, 4096, bnp);
    bnfin<<<1, 64>>>(bnp, eg0, ebb0, sc + 0*256, sf + 0*256, 64, 1.f/(16.f*4096.f));
    gconv<64, 128,  64,  64, true,  false><<<dim3(256, 2), 256>>>(y0, wt1, eb1, sc + 0*256, sf + 0*256, y1);
    bnpart<<<dim3(128, 8), 256>>>(y1, 128, 1024, bnp);
    bnfin<<<1, 128>>>(bnp, eg1, ebb1, sc + 1*256, sf + 1*256, 128, 1.f/(16.f*1024.f));
    gconv<128, 256, 32,  32, true,  false><<<dim3(64, 4),  256>>>(y1, wt2, eb2, sc + 1*256, sf + 1*256, y2);
    bnpart<<<dim3(256, 8), 256>>>(y2, 256, 256, bnp);
    bnfin<<<1, 256>>>(bnp, eg2, ebb2, sc + 2*256, sf + 2*256, 256, 1.f/(16.f*256.f));
    gconv<256, 256, 16,  16, true,  true ><<<dim3(16, 4, 4), 256>>>(y2, wt3, eb3, sc + 2*256, sf + 2*256, part);
    zcombine<<<512, 512>>>(part, eb3, z);

    // ---- vector quantizer ----
    vqk<<<1024, 256>>>(z, cb, cn, q, rl, out + 786434, out + 786434 + 1024);
    lossfin<<<1, 256>>>(rl, out);

    // ---- decoder ----
    gconvt<256, 128, 4,  8,  8, false><<<dim3(16,  32), 256>>>(q,  dw0, db0, nullptr, nullptr, d0);
    bnpart<<<dim3(128, 8), 256>>>(d0, 128, 1024, bnp);
    bnfin<<<1, 128>>>(bnp, dg0, dbb0, sc + 3*256, sf + 3*256, 128, 1.f/(16.f*1024.f));
    gconvt<128,  64, 2, 32, 32, true ><<<dim3(256,  4), 256>>>(d0, dw1, db1, sc + 3*256, sf + 3*256, d1);
    bnpart<<<dim3(64, 8),  256>>>(d1,  64, 4096, bnp);
    bnfin<<<1, 64>>>(bnp, dg1, dbb1, sc + 4*256, sf + 4*256, 64, 1.f/(16.f*4096.f));
    gconvt<64,   32, 2, 64, 64, true ><<<dim3(1024, 2), 256>>>(d1, dw2, db2, sc + 4*256, sf + 4*256, d2);
    bnpart<<<dim3(32, 8),  256>>>(d2,  32, 16384, bnp);
    bnfin<<<1, 32>>>(bnp, dg2, dbb2, sc + 5*256, sf + 5*256, 32, 1.f/(16.f*16384.f));

    final1x1<<<1024, 256>>>(d2, dw3, db3, sc + 5*256, sf + 5*256, out);
}

// round 7
// speedup vs baseline: 2.0069x; 1.1103x over previous
#include <cuda_runtime.h>
#include <cuda_bf16.h>
#include <math.h>

#define LEAKK 0.01f
#define EPSS  1e-5f

// packed fp32x2 FMA (FFMA2) — B300 only via PTX fma.rn.f32x2
#define FMA2(acc, a, b) \
    asm("fma.rn.f32x2 %0, %1, %2, %0;" : "+l"(acc) : "l"(a), "l"(b))

__device__ __forceinline__ float2 unpk(unsigned long long p) {
    unsigned int lo, hi;
    asm("mov.b64 {%0,%1}, %2;" : "=r"(lo), "=r"(hi) : "l"(p));
    return make_float2(__uint_as_float(lo), __uint_as_float(hi));
}

// ---------------- scratch (device globals; no allocation) ----------------
__device__ float g_y0[16*64*64*64];
__device__ float g_y1[16*128*32*32];
__device__ float g_y2[16*256*16*16];
__device__ float g_z [16*256*8*8];
__device__ float g_q [16*256*8*8];
__device__ float g_d0[16*128*32*32];
__device__ float g_d1[16*64*64*64];
__device__ float g_d2[16*32*128*128];
__device__ float g_wt[1707008];
__device__ float g_part[4194304];
__device__ float g_scale[6*256];
__device__ float g_shift[6*256];
__device__ float g_cnorm[512];
__device__ float g_rowloss[1024];
__device__ float2 g_bnp[256*8];

// ---------------- smem-tiled transpose: w[Co][K] -> wt[K][Co] ------------
__global__ void wtrans(const float* __restrict__ in, float* __restrict__ outp,
                       int R /*Co*/, int Ccol /*Ci*16*/) {
    __shared__ float t[32][33];
    int bx = blockIdx.x * 32, by = blockIdx.y * 32;
    int tx = threadIdx.x, ty = threadIdx.y;
#pragma unroll
    for (int j = 0; j < 4; j++) {
        int xx = bx + tx, yy = by + ty + j * 8;
        if (xx < Ccol && yy < R) t[ty + j * 8][tx] = in[yy * Ccol + xx];
    }
    __syncthreads();
#pragma unroll
    for (int j = 0; j < 4; j++) {
        int xx = by + tx, yy = bx + ty + j * 8;
        if (xx < R && yy < Ccol) outp[yy * R + xx] = t[tx][ty + j * 8];
    }
}

// ---------------- conv (k=4,s=2,p=1) 64co x 64px tile (enc0 only) --------
template<int CIN, int COUT, int H, int W, bool BN>
__global__ void __launch_bounds__(256)
gconv(const float* __restrict__ x, const float* __restrict__ wt,
      const float* __restrict__ bias,
      const float* __restrict__ scale, const float* __restrict__ shift,
      float* __restrict__ out) {
    constexpr int Ho = H / 2, Wo = W / 2, HoWo = Ho * Wo;
    constexpr int NCH = CIN;

    __shared__ float Asd[2][16][128];
    __shared__ float Bs [2][16][64];

    const int tid = threadIdx.x;
    const int tx = tid & 15, ty = tid >> 4;
    const int p0 = blockIdx.x * 64;
    const int co0 = blockIdx.y * 64;

    const int pp = tid & 63;
    const int cc = tid & 63;
    int kkj[4], boff[4];
    bool val[4];
    {
        int gp = p0 + pp;
        int b = gp / HoWo, r = gp % HoWo;
        int oh = r / Wo, ow = r % Wo;
#pragma unroll
        for (int j = 0; j < 4; j++) {
            int kk = (tid >> 6) + 4 * j;
            int kh = kk >> 2, kw = kk & 3;
            int ih = 2 * oh - 1 + kh, iw = 2 * ow - 1 + kw;
            val[j] = (ih >= 0) && (ih < H) && (iw >= 0) && (iw < W);
            kkj[j] = kk;
            boff[j] = (b * CIN + 0) * H * W + ih * W + iw;
        }
    }

    float bv[4], av[4];
    auto gather = [&](int c) {
        int ci = c;
        float sc = 1.f, sf = 0.f;
        if (BN) { sc = scale[ci]; sf = shift[ci]; }
#pragma unroll
        for (int j = 0; j < 4; j++) {
            float v = 0.f;
            if (val[j]) {
                v = x[boff[j] + ci * (H * W)];
                if (BN) { v = v * sc + sf; v = fmaxf(v, LEAKK * v); }
            }
            bv[j] = v;
            av[j] = wt[(ci * 16 + kkj[j]) * COUT + co0 + cc];
        }
    };
    auto stobuf = [&](int nb) {
#pragma unroll
        for (int j = 0; j < 4; j++) {
            Bs[nb][kkj[j]][pp] = bv[j];
            *(float2*)&Asd[nb][kkj[j]][2 * cc] = make_float2(av[j], av[j]);
        }
    };

    gather(0);
    stobuf(0);
    __syncthreads();

    unsigned long long acc[4][2];
#pragma unroll
    for (int i = 0; i < 4; i++) { acc[i][0] = 0ULL; acc[i][1] = 0ULL; }

    for (int c = 0; c < NCH; c++) {
        int cur = c & 1;
        bool more = (c + 1) < NCH;
        if (more) gather(c + 1);
#pragma unroll
        for (int k = 0; k < 16; k++) {
            ulonglong2 b2  = *(const ulonglong2*)&Bs [cur][k][4 * tx];
            ulonglong2 a01 = *(const ulonglong2*)&Asd[cur][k][8 * ty];
            ulonglong2 a23 = *(const ulonglong2*)&Asd[cur][k][8 * ty + 4];
            FMA2(acc[0][0], a01.x, b2.x); FMA2(acc[0][1], a01.x, b2.y);
            FMA2(acc[1][0], a01.y, b2.x); FMA2(acc[1][1], a01.y, b2.y);
            FMA2(acc[2][0], a23.x, b2.x); FMA2(acc[2][1], a23.x, b2.y);
            FMA2(acc[3][0], a23.y, b2.x); FMA2(acc[3][1], a23.y, b2.y);
        }
        if (more) stobuf(cur ^ 1);
        __syncthreads();
    }

    const int b = p0 / HoWo;
    const int rb = (p0 % HoWo) + 4 * tx;
#pragma unroll
    for (int i = 0; i < 4; i++) {
        int co = co0 + 4 * ty + i;
        float bvs = bias[co];
        float2 u0 = unpk(acc[i][0]);
        float2 u1 = unpk(acc[i][1]);
        float4 o = make_float4(u0.x + bvs, u0.y + bvs, u1.x + bvs, u1.y + bvs);
        *(float4*)&out[(b * COUT + co) * HoWo + rb] = o;
    }
}

// ---------------- conv as GEMM, 128co x 128px tile, optional K-split ------
template<int CIN, int COUT, int H, int W, bool BN, int NSPLIT>
__global__ void __launch_bounds__(256, 2)
gconv2(const float* __restrict__ x, const float* __restrict__ wt,
       const float* __restrict__ bias,
       const float* __restrict__ scale, const float* __restrict__ shift,
       float* __restrict__ out) {
    constexpr int Ho = H / 2, Wo = W / 2, HoWo = Ho * Wo;
    constexpr int NPIX = 16 * HoWo;
    constexpr int NCH = CIN / NSPLIT;

    __shared__ float Asd[2][16][256];
    __shared__ float Bs [2][16][128];

    const int tid = threadIdx.x;
    const int tx = tid & 15, ty = tid >> 4;
    const int p0 = blockIdx.x * 128;
    const int co0 = blockIdx.y * 128;
    const int ci0 = blockIdx.z * NCH;

    const int pb = tid & 127;
    const int gK = tid >> 7;   // 0/1

    const int gp = p0 + pb;
    const int bI = gp / HoWo, rI = gp % HoWo;
    const int oh = rI / Wo, ow = rI % Wo;
    const int ih0 = 2 * oh - 1, iw0 = 2 * ow - 1;
    const int xbase = bI * CIN * H * W;

    int boff[8]; unsigned vmask = 0;
#pragma unroll
    for (int j = 0; j < 8; j++) {
        int kk = gK + 2 * j;
        int kh = kk >> 2, kw = kk & 3;
        int ih = ih0 + kh, iw = iw0 + kw;
        if (ih >= 0 && ih < H && iw >= 0 && iw < W) vmask |= (1u << j);
        boff[j] = xbase + ih * W + iw;
    }

    float bv[8], av[8];
    auto gather = [&](int c) {
        int ci = ci0 + c;
        float sc_ = 1.f, sf_ = 0.f;
        if (BN) { sc_ = scale[ci]; sf_ = shift[ci]; }
        const float* wrow = wt + (ci * 16 + gK) * COUT + co0 + pb;
        const float* xch = x + ci * (H * W);
#pragma unroll
        for (int j = 0; j < 8; j++) {
            float v = 0.f;
            if (vmask & (1u << j)) {
                v = xch[boff[j]];
                if (BN) { v = v * sc_ + sf_; v = fmaxf(v, LEAKK * v); }
            }
            bv[j] = v;
            av[j] = wrow[2 * j * COUT];
        }
    };
    auto stobuf = [&](int nb) {
#pragma unroll
        for (int j = 0; j < 8; j++) {
            int kk = gK + 2 * j;
            Bs[nb][kk][pb] = bv[j];
            *(float2*)&Asd[nb][kk][2 * pb] = make_float2(av[j], av[j]);
        }
    };

    gather(0);
    stobuf(0);
    __syncthreads();

    unsigned long long acc[8][4];
#pragma unroll
    for (int i = 0; i < 8; i++)
#pragma unroll
        for (int l = 0; l < 4; l++) acc[i][l] = 0ULL;

    for (int c = 0; c < NCH; c++) {
        int cur = c & 1;
        bool more = (c + 1) < NCH;
        if (more) gather(c + 1);
#pragma unroll
        for (int k = 0; k < 16; k++) {
            ulonglong2 b01 = *(const ulonglong2*)&Bs [cur][k][8 * tx];
            ulonglong2 b23 = *(const ulonglong2*)&Bs [cur][k][8 * tx + 4];
            ulonglong2 a01 = *(const ulonglong2*)&Asd[cur][k][16 * ty];
            ulonglong2 a23 = *(const ulonglong2*)&Asd[cur][k][16 * ty + 4];
            ulonglong2 a45 = *(const ulonglong2*)&Asd[cur][k][16 * ty + 8];
            ulonglong2 a67 = *(const ulonglong2*)&Asd[cur][k][16 * ty + 12];
            FMA2(acc[0][0], a01.x, b01.x); FMA2(acc[0][1], a01.x, b01.y);
            FMA2(acc[0][2], a01.x, b23.x); FMA2(acc[0][3], a01.x, b23.y);
            FMA2(acc[1][0], a01.y, b01.x); FMA2(acc[1][1], a01.y, b01.y);
            FMA2(acc[1][2], a01.y, b23.x); FMA2(acc[1][3], a01.y, b23.y);
            FMA2(acc[2][0], a23.x, b01.x); FMA2(acc[2][1], a23.x, b01.y);
            FMA2(acc[2][2], a23.x, b23.x); FMA2(acc[2][3], a23.x, b23.y);
            FMA2(acc[3][0], a23.y, b01.x); FMA2(acc[3][1], a23.y, b01.y);
            FMA2(acc[3][2], a23.y, b23.x); FMA2(acc[3][3], a23.y, b23.y);
            FMA2(acc[4][0], a45.x, b01.x); FMA2(acc[4][1], a45.x, b01.y);
            FMA2(acc[4][2], a45.x, b23.x); FMA2(acc[4][3], a45.x, b23.y);
            FMA2(acc[5][0], a45.y, b01.x); FMA2(acc[5][1], a45.y, b01.y);
            FMA2(acc[5][2], a45.y, b23.x); FMA2(acc[5][3], a45.y, b23.y);
            FMA2(acc[6][0], a67.x, b01.x); FMA2(acc[6][1], a67.x, b01.y);
            FMA2(acc[6][2], a67.x, b23.x); FMA2(acc[6][3], a67.x, b23.y);
            FMA2(acc[7][0], a67.y, b01.x); FMA2(acc[7][1], a67.y, b01.y);
            FMA2(acc[7][2], a67.y, b23.x); FMA2(acc[7][3], a67.y, b23.y);
        }
        if (more) stobuf(cur ^ 1);
        __syncthreads();
    }

    const int gpo = p0 + 8 * tx;
    const int b = gpo / HoWo, rb = gpo % HoWo;
    float* po = out + (NSPLIT > 1 ? blockIdx.z * (NPIX * COUT) : 0);
#pragma unroll
    for (int i = 0; i < 8; i++) {
        int co = co0 + 8 * ty + i;
        float bvs = (NSPLIT > 1) ? 0.f : bias[co];
        float2 u0 = unpk(acc[i][0]);
        float2 u1 = unpk(acc[i][1]);
        float2 u2 = unpk(acc[i][2]);
        float2 u3 = unpk(acc[i][3]);
        int idx = (b * COUT + co) * HoWo + rb;
        *(float4*)&po[idx]     = make_float4(u0.x + bvs, u0.y + bvs, u1.x + bvs, u1.y + bvs);
        *(float4*)&po[idx + 4] = make_float4(u2.x + bvs, u2.y + bvs, u3.x + bvs, u3.y + bvs);
    }
}

// ---------------- ConvTranspose as GEMM, 128m x 128px tile ----------------
template<int CIN, int COUT, int K, int H, int W, bool BN, int NSPLIT>
__global__ void __launch_bounds__(256, 2)
gconvt2(const float* __restrict__ x, const float* __restrict__ w,
        const float* __restrict__ bias,
        const float* __restrict__ scale, const float* __restrict__ shift,
        float* __restrict__ out) {
    constexpr int HW = H * W;
    constexpr int KK = K * K;
    constexpr int M = COUT * KK;
    constexpr int Hout = H * K, Wout = W * K;
    constexpr int NCH = (CIN / NSPLIT) / 16;
    constexpr int SLICE = 16 * COUT * Hout * Wout;

    __shared__ float Asd[2][16][256];
    __shared__ float Bs [2][16][128];

    const int tid = threadIdx.x;
    const int tx = tid & 15, ty = tid >> 4;
    const int p0 = blockIdx.x * 128;
    const int m0 = blockIdx.y * 128;
    const int cbase = blockIdx.z * (CIN / NSPLIT);

    const int pb = tid & 127;
    const int gK = tid >> 7;

    const int gp = p0 + pb;
    const int bI = gp / HW, rI = gp % HW;
    const int xrow = bI * CIN * HW + rI;

    float bv[8], av[8];
    auto gather = [&](int c) {
        int c0 = cbase + c * 16 + gK;
#pragma unroll
        for (int j = 0; j < 8; j++) {
            int ch = c0 + 2 * j;
            float v = x[xrow + ch * HW];
            if (BN) {
                float t = v * scale[ch] + shift[ch];
                v = fmaxf(t, LEAKK * t);
            }
            bv[j] = v;
            av[j] = w[ch * M + m0 + pb];
        }
    };
    auto stobuf = [&](int nb) {
#pragma unroll
        for (int j = 0; j < 8; j++) {
            int kk = gK + 2 * j;
            Bs[nb][kk][pb] = bv[j];
            *(float2*)&Asd[nb][kk][2 * pb] = make_float2(av[j], av[j]);
        }
    };

    gather(0);
    stobuf(0);
    __syncthreads();

    unsigned long long acc[8][4];
#pragma unroll
    for (int i = 0; i < 8; i++)
#pragma unroll
        for (int l = 0; l < 4; l++) acc[i][l] = 0ULL;

    for (int c = 0; c < NCH; c++) {
        int cur = c & 1;
        bool more = (c + 1) < NCH;
        if (more) gather(c + 1);
#pragma unroll
        for (int k = 0; k < 16; k++) {
            ulonglong2 b01 = *(const ulonglong2*)&Bs [cur][k][8 * tx];
            ulonglong2 b23 = *(const ulonglong2*)&Bs [cur][k][8 * tx + 4];
            ulonglong2 a01 = *(const ulonglong2*)&Asd[cur][k][16 * ty];
            ulonglong2 a23 = *(const ulonglong2*)&Asd[cur][k][16 * ty + 4];
            ulonglong2 a45 = *(const ulonglong2*)&Asd[cur][k][16 * ty + 8];
            ulonglong2 a67 = *(const ulonglong2*)&Asd[cur][k][16 * ty + 12];
            FMA2(acc[0][0], a01.x, b01.x); FMA2(acc[0][1], a01.x, b01.y);
            FMA2(acc[0][2], a01.x, b23.x); FMA2(acc[0][3], a01.x, b23.y);
            FMA2(acc[1][0], a01.y, b01.x); FMA2(acc[1][1], a01.y, b01.y);
            FMA2(acc[1][2], a01.y, b23.x); FMA2(acc[1][3], a01.y, b23.y);
            FMA2(acc[2][0], a23.x, b01.x); FMA2(acc[2][1], a23.x, b01.y);
            FMA2(acc[2][2], a23.x, b23.x); FMA2(acc[2][3], a23.x, b23.y);
            FMA2(acc[3][0], a23.y, b01.x); FMA2(acc[3][1], a23.y, b01.y);
            FMA2(acc[3][2], a23.y, b23.x); FMA2(acc[3][3], a23.y, b23.y);
            FMA2(acc[4][0], a45.x, b01.x); FMA2(acc[4][1], a45.x, b01.y);
            FMA2(acc[4][2], a45.x, b23.x); FMA2(acc[4][3], a45.x, b23.y);
            FMA2(acc[5][0], a45.y, b01.x); FMA2(acc[5][1], a45.y, b01.y);
            FMA2(acc[5][2], a45.y, b23.x); FMA2(acc[5][3], a45.y, b23.y);
            FMA2(acc[6][0], a67.x, b01.x); FMA2(acc[6][1], a67.x, b01.y);
            FMA2(acc[6][2], a67.x, b23.x); FMA2(acc[6][3], a67.x, b23.y);
            FMA2(acc[7][0], a67.y, b01.x); FMA2(acc[7][1], a67.y, b01.y);
            FMA2(acc[7][2], a67.y, b23.x); FMA2(acc[7][3], a67.y, b23.y);
        }
        if (more) stobuf(cur ^ 1);
        __syncthreads();
    }

    const int gpo = p0 + 8 * tx;
    const int b = gpo / HW, rr = gpo % HW;
    float* po = out + (NSPLIT > 1 ? blockIdx.z * SLICE : 0);
    int ihh[8], iww[8];
#pragma unroll
    for (int l = 0; l < 8; l++) { ihh[l] = (rr + l) / W; iww[l] = (rr + l) % W; }
#pragma unroll
    for (int i = 0; i < 8; i++) {
        int m = m0 + 8 * ty + i;
        int co = m / KK, rem = m % KK;
        int ki = rem / K, kj = rem % K;
        float bvs = (NSPLIT > 1) ? 0.f : bias[co];
        float2 u0 = unpk(acc[i][0]);
        float2 u1 = unpk(acc[i][1]);
        float2 u2 = unpk(acc[i][2]);
        float2 u3 = unpk(acc[i][3]);
        float f[8] = {u0.x, u0.y, u1.x, u1.y, u2.x, u2.y, u3.x, u3.y};
#pragma unroll
        for (int l = 0; l < 8; l++) {
            po[((b * COUT + co) * Hout + ihh[l] * K + ki) * Wout + iww[l] * K + kj]
                = f[l] + bvs;
        }
    }
}

// ---------------- K-split combine: sum slices + bias ----------------------
__global__ void combine(const float* __restrict__ part, const float* __restrict__ bias,
                        float* __restrict__ out, int len, int S, int HWo, int CO) {
    int i = blockIdx.x * blockDim.x + threadIdx.x;
    if (i >= len) return;
    float s = 0.f;
    for (int k = 0; k < S; k++) s += part[i + k * len];
    int co = (i / HWo) % CO;
    out[i] = s + bias[co];
}

// ---------------- BN batch stats: two-phase ------------------------------
__global__ void bnpart(const float* __restrict__ y, int C, int HW,
                       float2* __restrict__ part) {
    int c = blockIdx.x, s = blockIdx.y;
    int seg = HW / 8, r0 = s * seg;
    float sm = 0.f, s2 = 0.f;
    for (int b = 0; b < 16; b++) {
        const float* p = y + (b * C + c) * HW;
        for (int r = r0 + threadIdx.x; r < r0 + seg; r += 256) {
            float v = p[r];
            sm += v; s2 += v * v;
        }
    }
    __shared__ float sh[256], sh2[256];
    sh[threadIdx.x] = sm; sh2[threadIdx.x] = s2;
    __syncthreads();
    for (int o = 128; o > 0; o >>= 1) {
        if (threadIdx.x < o) { sh[threadIdx.x] += sh[threadIdx.x + o];
                               sh2[threadIdx.x] += sh2[threadIdx.x + o]; }
        __syncthreads();
    }
    if (threadIdx.x == 0) part[c * 8 + s] = make_float2(sh[0], sh2[0]);
}

__global__ void bnfin(const float2* __restrict__ part,
                      const float* __restrict__ g, const float* __restrict__ bb,
                      float* __restrict__ scale, float* __restrict__ shift,
                      int C, float invn) {
    int c = threadIdx.x;
    if (c >= C) return;
    float sm = 0.f, s2 = 0.f;
#pragma unroll
    for (int s = 0; s < 8; s++) { float2 p = part[c * 8 + s]; sm += p.x; s2 += p.y; }
    float m = sm * invn;
    float v = s2 * invn - m * m;
    float sc = g[c] * rsqrtf(v + EPSS);
    scale[c] = sc;
    shift[c] = bb[c] - m * sc;
}

// ---------------- codebook squared norms ----------------------------------
__global__ void cnormk(const float* __restrict__ cb, float* __restrict__ cn) {
    int c = blockIdx.x;
    float v = cb[c * 256 + threadIdx.x];
    __shared__ float sh[256];
    sh[threadIdx.x] = v * v;
    __syncthreads();
    for (int o = 128; o > 0; o >>= 1) {
        if (threadIdx.x < o) sh[threadIdx.x] += sh[threadIdx.x + o];
        __syncthreads();
    }
    if (threadIdx.x == 0) cn[c] = sh[0];
}

// ---------------- vector quantizer ---------------------------------------
__global__ void vqk(const float* __restrict__ z, const float* __restrict__ cb,
                    const float* __restrict__ cn, float* __restrict__ q,
                    float* __restrict__ rowloss,
                    float* __restrict__ out_idx, float* __restrict__ out_mind) {
    int row = blockIdx.x;
    int b = row >> 6, hw = row & 63;
    int tid = threadIdx.x, lane = tid & 31, warp = tid >> 5;
    __shared__ float zf[256];
    __shared__ float red[256];

    zf[tid] = z[(b * 256 + tid) * 64 + hw];
    red[tid] = zf[tid] * zf[tid];
    __syncthreads();
    for (int o = 128; o > 0; o >>= 1) {
        if (tid < o) red[tid] += red[tid + o];
        __syncthreads();
    }
    float znorm = red[0];
    __syncthreads();

    float best = 3.4e38f; int bidx = 1 << 20;
    for (int code = warp; code < 512; code += 8) {
        const float* cr = cb + code * 256;
        float dot = 0.f;
#pragma unroll
        for (int k = 0; k < 8; k++) dot += cr[lane + 32 * k] * zf[lane + 32 * k];
#pragma unroll
        for (int o = 16; o > 0; o >>= 1) dot += __shfl_down_sync(0xffffffffu, dot, o);
        if (lane == 0) {
            float d2 = znorm - 2.f * dot + cn[code];
            if (d2 < best || (d2 == best && code < bidx)) { best = d2; bidx = code; }
        }
    }
    __shared__ float wbest[8]; __shared__ int widx[8];
    if (lane == 0) { wbest[warp] = best; widx[warp] = bidx; }
    __syncthreads();
    if (tid == 0) {
        float bb = wbest[0]; int bi = widx[0];
        for (int w = 1; w < 8; w++)
            if (wbest[w] < bb || (wbest[w] == bb && widx[w] < bi)) { bb = wbest[w]; bi = widx[w]; }
        wbest[0] = bb; widx[0] = bi;
    }
    __syncthreads();
    int idx = widx[0];
    float mind = wbest[0];

    float qv = cb[idx * 256 + tid];
    q[(b * 256 + tid) * 64 + hw] = qv;
    float diff = qv - zf[tid];
    red[tid] = diff * diff;
    __syncthreads();
    for (int o = 128; o > 0; o >>= 1) {
        if (tid < o) red[tid] += red[tid + o];
        __syncthreads();
    }
    if (tid == 0) {
        rowloss[row] = red[0];
        out_idx[row] = (float)idx;
        out_mind[row] = mind;
    }
}

__global__ void lossfin(const float* __restrict__ rowloss, float* __restrict__ out) {
    __shared__ float sh[256];
    float s = 0.f;
    for (int i = threadIdx.x; i < 1024; i += 256) s += rowloss[i];
    sh[threadIdx.x] = s; __syncthreads();
    for (int o = 128; o > 0; o >>= 1) {
        if (threadIdx.x < o) sh[threadIdx.x] += sh[threadIdx.x + o];
        __syncthreads();
    }
    if (threadIdx.x == 0) {
        float L = sh[0] / (1024.f * 256.f);
        out[786432] = L;
        out[786433] = L;
    }
}

// ---------------- final 1x1 conv + tanh, fused input BN+LReLU ------------
__global__ void final1x1(const float* __restrict__ h, const float* __restrict__ w3,
                         const float* __restrict__ b3,
                         const float* __restrict__ scale, const float* __restrict__ shift,
                         float* __restrict__ out) {
    __shared__ float sw[96], ssc[32], ssh[32], sb[3];
    if (threadIdx.x < 96) sw[threadIdx.x] = w3[threadIdx.x];
    if (threadIdx.x < 32) { ssc[threadIdx.x] = scale[threadIdx.x];
                            ssh[threadIdx.x] = shift[threadIdx.x]; }
    if (threadIdx.x < 3) sb[threadIdx.x] = b3[threadIdx.x];
    __syncthreads();
    const int HW = 128 * 128;
    int gid = blockIdx.x * blockDim.x + threadIdx.x;
    int b = gid / HW, r = gid % HW;
    float a0 = 0.f, a1 = 0.f, a2 = 0.f;
#pragma unroll 8
    for (int c = 0; c < 32; c++) {
        float v = h[(b * 32 + c) * HW + r];
        v = v * ssc[c] + ssh[c];
        v = fmaxf(v, LEAKK * v);
        a0 += v * sw[c];
        a1 += v * sw[32 + c];
        a2 += v * sw[64 + c];
    }
    out[(b * 3 + 0) * HW + r] = tanhf(a0 + sb[0]);
    out[(b * 3 + 1) * HW + r] = tanhf(a1 + sb[1]);
    out[(b * 3 + 2) * HW + r] = tanhf(a2 + sb[2]);
}

// ------------------------------------------------------------------------
extern "C" void kernel_launch(void* const* d_in, const int* in_sizes, int n_in,
                              void* d_out, int out_size) {
    (void)n_in; (void)out_size;

    const float* x = (const float*)d_in[0];
    const float *ew0, *eb0, *eg0, *ebb0;
    const float *ew1, *eb1, *eg1, *ebb1;
    const float *ew2, *eb2, *eg2, *ebb2;
    const float *ew3, *eb3;

    if (in_sizes[3] == 64) {
        ew0 = (const float*)d_in[1];  eb0 = (const float*)d_in[2];
        eg0 = (const float*)d_in[3];  ebb0 = (const float*)d_in[4];
        ew1 = (const float*)d_in[5];  eb1 = (const float*)d_in[6];
        eg1 = (const float*)d_in[7];  ebb1 = (const float*)d_in[8];
        ew2 = (const float*)d_in[9];  eb2 = (const float*)d_in[10];
        eg2 = (const float*)d_in[11]; ebb2 = (const float*)d_in[12];
        ew3 = (const float*)d_in[13]; eb3 = (const float*)d_in[14];
    } else {
        ew0 = (const float*)d_in[1];  eb0 = (const float*)d_in[2];
        ew1 = (const float*)d_in[3];  eb1 = (const float*)d_in[4];
        ew2 = (const float*)d_in[5];  eb2 = (const float*)d_in[6];
        ew3 = (const float*)d_in[7];  eb3 = (const float*)d_in[8];
        eg0 = (const float*)d_in[9];  ebb0 = (const float*)d_in[10];
        eg1 = (const float*)d_in[11]; ebb1 = (const float*)d_in[12];
        eg2 = (const float*)d_in[13]; ebb2 = (const float*)d_in[14];
    }

    const float* cb   = (const float*)d_in[15];
    const float* dw0  = (const float*)d_in[16];
    const float* db0  = (const float*)d_in[17];
    const float* dg0  = (const float*)d_in[18];
    const float* dbb0 = (const float*)d_in[19];
    const float* dw1  = (const float*)d_in[20];
    const float* db1  = (const float*)d_in[21];
    const float* dg1  = (const float*)d_in[22];
    const float* dbb1 = (const float*)d_in[23];
    const float* dw2  = (const float*)d_in[24];
    const float* db2  = (const float*)d_in[25];
    const float* dg2  = (const float*)d_in[26];
    const float* dbb2 = (const float*)d_in[27];
    const float* dw3  = (const float*)d_in[28];
    const float* db3  = (const float*)d_in[29];
    float* out = (float*)d_out;

    float *y0, *y1, *y2, *z, *q, *d0, *d1, *d2, *wt, *part, *sc, *sf, *cn, *rl;
    float2* bnp;
    cudaGetSymbolAddress((void**)&y0, g_y0);
    cudaGetSymbolAddress((void**)&y1, g_y1);
    cudaGetSymbolAddress((void**)&y2, g_y2);
    cudaGetSymbolAddress((void**)&z,  g_z);
    cudaGetSymbolAddress((void**)&q,  g_q);
    cudaGetSymbolAddress((void**)&d0, g_d0);
    cudaGetSymbolAddress((void**)&d1, g_d1);
    cudaGetSymbolAddress((void**)&d2, g_d2);
    cudaGetSymbolAddress((void**)&wt, g_wt);
    cudaGetSymbolAddress((void**)&part, g_part);
    cudaGetSymbolAddress((void**)&sc, g_scale);
    cudaGetSymbolAddress((void**)&sf, g_shift);
    cudaGetSymbolAddress((void**)&cn, g_cnorm);
    cudaGetSymbolAddress((void**)&rl, g_rowloss);
    cudaGetSymbolAddress((void**)&bnp, g_bnp);

    float* wt0 = wt;
    float* wt1 = wt + 3072;
    float* wt2 = wt + 134144;
    float* wt3 = wt + 658432;

    dim3 t32(32, 8);
    wtrans<<<dim3(2,   2), t32>>>(ew0, wt0,  64,   48);
    wtrans<<<dim3(32,  4), t32>>>(ew1, wt1, 128, 1024);
    wtrans<<<dim3(64,  8), t32>>>(ew2, wt2, 256, 2048);
    wtrans<<<dim3(128, 8), t32>>>(ew3, wt3, 256, 4096);
    cnormk<<<512, 256>>>(cb, cn);

    // ---- encoder ----
    gconv<3, 64, 128, 128, false><<<dim3(1024, 1), 256>>>(x, wt0, eb0, nullptr, nullptr, y0);
    bnpart<<<dim3(64, 8),  256>>>(y0,  64, 4096, bnp);
    bnfin<<<1, 64>>>(bnp, eg0, ebb0, sc + 0*256, sf + 0*256, 64, 1.f/(16.f*4096.f));

    gconv2<64, 128, 64, 64, true, 2><<<dim3(128, 1, 2), 256>>>(y0, wt1, eb1, sc + 0*256, sf + 0*256, part);
    combine<<<8192, 256>>>(part, eb1, y1, 2097152, 2, 1024, 128);
    bnpart<<<dim3(128, 8), 256>>>(y1, 128, 1024, bnp);
    bnfin<<<1, 128>>>(bnp, eg1, ebb1, sc + 1*256, sf + 1*256, 128, 1.f/(16.f*1024.f));

    gconv2<128, 256, 32, 32, true, 4><<<dim3(32, 2, 4), 256>>>(y1, wt2, eb2, sc + 1*256, sf + 1*256, part);
    combine<<<4096, 256>>>(part, eb2, y2, 1048576, 4, 256, 256);
    bnpart<<<dim3(256, 8), 256>>>(y2, 256, 256, bnp);
    bnfin<<<1, 256>>>(bnp, eg2, ebb2, sc + 2*256, sf + 2*256, 256, 1.f/(16.f*256.f));

    gconv2<256, 256, 16, 16, true, 16><<<dim3(8, 2, 16), 256>>>(y2, wt3, eb3, sc + 2*256, sf + 2*256, part);
    combine<<<1024, 256>>>(part, eb3, z, 262144, 16, 64, 256);

    // ---- vector quantizer ----
    vqk<<<1024, 256>>>(z, cb, cn, q, rl, out + 786434, out + 786434 + 1024);
    lossfin<<<1, 256>>>(rl, out);

    // ---- decoder ----
    gconvt2<256, 128, 4,  8,  8, false, 2><<<dim3(8, 16, 2), 256>>>(q, dw0, db0, nullptr, nullptr, part);
    combine<<<8192, 256>>>(part, db0, d0, 2097152, 2, 1024, 128);
    bnpart<<<dim3(128, 8), 256>>>(d0, 128, 1024, bnp);
    bnfin<<<1, 128>>>(bnp, dg0, dbb0, sc + 3*256, sf + 3*256, 128, 1.f/(16.f*1024.f));

    gconvt2<128, 64, 2, 32, 32, true, 1><<<dim3(128, 2, 1), 256>>>(d0, dw1, db1, sc + 3*256, sf + 3*256, d1);
    bnpart<<<dim3(64, 8),  256>>>(d1,  64, 4096, bnp);
    bnfin<<<1, 64>>>(bnp, dg1, dbb1, sc + 4*256, sf + 4*256, 64, 1.f/(16.f*4096.f));

    gconvt2<64, 32, 2, 64, 64, true, 1><<<dim3(512, 1, 1), 256>>>(d1, dw2, db2, sc + 4*256, sf + 4*256, d2);
    bnpart<<<dim3(32, 8),  256>>>(d2,  32, 16384, bnp);
    bnfin<<<1, 32>>>(bnp, dg2, dbb2, sc + 5*256, sf + 5*256, 32, 1.f/(16.f*16384.f));

    final1x1<<<1024, 256>>>(d2, dw3, db3, sc + 5*256, sf + 5*256, out);
}